// round 13
// baseline (speedup 1.0000x reference)
#include <cuda_runtime.h>
#include <cuda_fp16.h>
#include <cstdint>
#include <cstddef>

#define BB 128
#define SS 1024
#define II 512
#define HH 1024
#define GG 4096
#define NCTA2 128

__device__ __half g_x_h[(size_t)BB * SS * II];
__device__ __half g_Wx_h[(size_t)GG * II];
__device__ __half g_Wh_h[(size_t)GG * HH];
__device__ float  g_bsum[GG];
__device__ __half g_xg[(size_t)SS * BB * GG];   // [S][B][4H]
__device__ __half g_h16[2][BB * HH];
__device__ float  g_h32[BB * HH];
// fine-grained producer flags: 16 groups (ms*8+kc), each padded to its own 128B line
__device__ unsigned g_wcnt[16 * 32];

__device__ __forceinline__ uint32_t smem_u32(const void* p) {
    return (uint32_t)__cvta_generic_to_shared(p);
}
__device__ __forceinline__ void cp_async16(void* dst, const void* src) {
    // .cg: bypass L1 (h is written by other SMs; L1 is per-SM incoherent)
    asm volatile("cp.async.cg.shared.global [%0], [%1], 16;\n" ::"r"(smem_u32(dst)), "l"(src));
}
__device__ __forceinline__ void cp_commit() { asm volatile("cp.async.commit_group;\n"); }
template <int N>
__device__ __forceinline__ void cp_wait() { asm volatile("cp.async.wait_group %0;\n" ::"n"(N)); }

__device__ __forceinline__ void ldsm_x4(uint32_t (&r)[4], const void* p) {
    asm volatile("ldmatrix.sync.aligned.m8n8.x4.shared.b16 {%0,%1,%2,%3}, [%4];\n"
                 : "=r"(r[0]), "=r"(r[1]), "=r"(r[2]), "=r"(r[3]) : "r"(smem_u32(p)));
}
__device__ __forceinline__ void mma16816(float (&d)[4], const uint32_t (&a)[4],
                                         uint32_t b0, uint32_t b1) {
    asm volatile("mma.sync.aligned.m16n8k16.row.col.f32.f16.f16.f32 "
                 "{%0,%1,%2,%3}, {%4,%5,%6,%7}, {%8,%9}, {%0,%1,%2,%3};\n"
                 : "+f"(d[0]), "+f"(d[1]), "+f"(d[2]), "+f"(d[3])
                 : "r"(a[0]), "r"(a[1]), "r"(a[2]), "r"(a[3]), "r"(b0), "r"(b1));
}
__device__ __forceinline__ float tanh_a(float x) {
    float y; asm("tanh.approx.f32 %0, %1;" : "=f"(y) : "f"(x)); return y;
}
__device__ __forceinline__ float sigm(float x) { return fmaf(tanh_a(0.5f * x), 0.5f, 0.5f); }
__device__ __forceinline__ unsigned ld_acq(const unsigned* p) {
    unsigned v;
    asm volatile("ld.acquire.gpu.b32 %0, [%1];" : "=r"(v) : "l"(p) : "memory");
    return v;
}

// ---------------- init ----------------
__global__ void lstm_prep_w(const float* __restrict__ Wx, const float* __restrict__ Wh,
                            const float* __restrict__ bW, const float* __restrict__ bU) {
    int stride = gridDim.x * blockDim.x;
    int i0 = blockIdx.x * blockDim.x + threadIdx.x;
    for (int i = i0; i < GG * HH; i += stride) g_Wh_h[i] = __float2half(Wh[i]);
    for (int i = i0; i < GG * II; i += stride) g_Wx_h[i] = __float2half(Wx[i]);
    if (i0 < GG) g_bsum[i0] = bW[i0] + bU[i0];
    if (i0 < BB * HH) { g_h16[0][i0] = __float2half(0.f); g_h16[1][i0] = __float2half(0.f); }
    if (i0 < 16 * 32) g_wcnt[i0] = 0u;
}
__global__ void lstm_prep_x(const float* __restrict__ x) {
    int stride = gridDim.x * blockDim.x;
    for (int i = blockIdx.x * blockDim.x + threadIdx.x; i < BB * SS * II; i += stride)
        g_x_h[i] = __float2half(x[i]);
}

// ---------------- phase 1: xg = x @ Wx^T + bsum (unchanged, known-good) ----------------
#define P1_SMEM (2 * 2 * 128 * 72 * 2)
__global__ void __launch_bounds__(256) lstm_xproj() {
    extern __shared__ __half sm1[];
    __half* As = sm1;
    __half* Bs = sm1 + 2 * 128 * 72;
    const int tid = threadIdx.x, lane = tid & 31, wid = tid >> 5;
    const int wm = wid >> 1, wn = wid & 1;
    const int n0 = blockIdx.x * 128, sblk = blockIdx.y;
    float acc[2][8][4];
#pragma unroll
    for (int mi = 0; mi < 2; ++mi)
#pragma unroll
        for (int f = 0; f < 8; ++f)
#pragma unroll
            for (int u = 0; u < 4; ++u) acc[mi][f][u] = 0.f;
#define P1_LOAD(buf, kc)                                                           \
    {                                                                              \
        int k0_ = (kc) * 64;                                                       \
        _Pragma("unroll") for (int it = 0; it < 4; ++it) {                         \
            int task = tid + it * 256, row = task >> 3, seg = task & 7;            \
            cp_async16(&As[(buf) * 9216 + row * 72 + seg * 8],                     \
                       g_x_h + ((size_t)row * SS + sblk) * II + k0_ + seg * 8);    \
            cp_async16(&Bs[(buf) * 9216 + row * 72 + seg * 8],                     \
                       g_Wx_h + (size_t)(n0 + row) * II + k0_ + seg * 8);          \
        }                                                                          \
    }
    P1_LOAD(0, 0);
    cp_commit();
#pragma unroll 1
    for (int kc = 0; kc < 8; ++kc) {
        int buf = kc & 1;
        if (kc < 7) { P1_LOAD(buf ^ 1, kc + 1); cp_commit(); cp_wait<1>(); }
        else        { cp_wait<0>(); }
        __syncthreads();
#pragma unroll
        for (int kk = 0; kk < 4; ++kk) {
            uint32_t a[2][4];
#pragma unroll
            for (int mi = 0; mi < 2; ++mi)
                ldsm_x4(a[mi], &As[buf * 9216 + (wm * 32 + mi * 16 + (lane & 15)) * 72 +
                                   kk * 16 + (lane >> 4) * 8]);
#pragma unroll
            for (int nj = 0; nj < 4; ++nj) {
                uint32_t b4[4];
                ldsm_x4(b4, &Bs[buf * 9216 + (wn * 64 + nj * 16 + (lane & 15)) * 72 +
                                kk * 16 + (lane >> 4) * 8]);
#pragma unroll
                for (int mi = 0; mi < 2; ++mi) {
                    mma16816(acc[mi][nj * 2 + 0], a[mi], b4[0], b4[2]);
                    mma16816(acc[mi][nj * 2 + 1], a[mi], b4[1], b4[3]);
                }
            }
        }
        __syncthreads();
    }
    const int r = lane >> 2, c2 = (lane & 3) * 2;
    const size_t mbase = (size_t)sblk * 128;
#pragma unroll
    for (int mi = 0; mi < 2; ++mi) {
        int mrow = wm * 32 + mi * 16 + r;
#pragma unroll
        for (int f = 0; f < 8; ++f) {
            int col = n0 + wn * 64 + f * 8 + c2;
            float b0 = g_bsum[col], b1 = g_bsum[col + 1];
            *(__half2*)(g_xg + (mbase + mrow) * (size_t)GG + col) =
                __floats2half2_rn(acc[mi][f][0] + b0, acc[mi][f][1] + b1);
            *(__half2*)(g_xg + (mbase + mrow + 8) * (size_t)GG + col) =
                __floats2half2_rn(acc[mi][f][2] + b0, acc[mi][f][3] + b1);
        }
    }
}

// ---------------- phase 2: persistent recurrence with fine-grained chunk flags ----------------
// 128 CTAs: ms = blk>>6 (64 B-rows), ns = blk&63 (16 h-cols -> 64 gate rows).
// 16 warps: kh = wid&1 (K half), wn = (wid>>1)&3, wm = wid>>3.
// No global barrier: consumer of h-chunk kc at step t waits g_wcnt[ms*8+kc] >= 8*t.
// Producer (ms,ns) increments g_wcnt[ms*8+(ns>>3)] after fenced h(t) store.
// Skew within an ms group is bounded by 1 step -> 2-buffer h ping-pong is WAR-safe.
#define WHS_STRIDE 1032
#define HCH_STRIDE 136
#define GS_STRIDE  68
#define HBUF (64 * HCH_STRIDE)
#define P2_SMEM (132096 + 4 * 17408) /* 201728 B -> 1 CTA/SM */

__global__ void __launch_bounds__(512, 1) lstm_rec() {
    extern __shared__ unsigned char smraw[];
    __half* Whs = (__half*)smraw;
    __half* Hs  = (__half*)(smraw + 132096);
    float*  Gs0 = (float*)(smraw + 132096);            // aliases h buf0 (dead when written)
    float*  Gs1 = (float*)(smraw + 132096 + 17408);    // aliases h buf1
    const int tid = threadIdx.x, lane = tid & 31, wid = tid >> 5;
    const int kh = wid & 1, wn = (wid >> 1) & 3, wm = wid >> 3;
    const int ms = blockIdx.x >> 6, ns = blockIdx.x & 63;
    unsigned* const myflag = &g_wcnt[(ms * 8 + (ns >> 3)) * 32];
    const unsigned* const flg = &g_wcnt[ms * 8 * 32];

    // resident Wh slice: row j -> gate (j>>4), h-col ns*16+(j&15)
#pragma unroll 4
    for (int it = 0; it < 16; ++it) {
        int task = tid + it * 512;
        int j = task >> 7, seg = task & 127;
        int grow = (j >> 4) * HH + ns * 16 + (j & 15);
        cp_async16(&Whs[j * WHS_STRIDE + seg * 8], g_Wh_h + (size_t)grow * HH + seg * 8);
    }
    cp_commit();
    cp_wait<0>();
    __syncthreads();

    const int hc = tid & 15, brow0 = tid >> 4;   // cells (brow0,hc),(brow0+32,hc)
    float cst[2] = {0.f, 0.f};

#define H_LOAD(buf, kc)                                                            \
    {                                                                              \
        _Pragma("unroll") for (int it = 0; it < 2; ++it) {                         \
            int task = tid + it * 512, row = task >> 4, seg = task & 15;           \
            cp_async16(&Hs[(buf) * HBUF + row * HCH_STRIDE + seg * 8],             \
                       hsrc + (size_t)row * HH + (kc) * 128 + seg * 8);            \
        }                                                                          \
        cp_commit();                                                               \
    }
#define XG_PREFETCH(tt)                                                            \
    {                                                                              \
        const __half* xp = g_xg + ((size_t)(tt) * BB + ms * 64) * GG + ns * 16 + hc; \
        _Pragma("unroll") for (int k = 0; k < 2; ++k) {                            \
            size_t bo = (size_t)(brow0 + k * 32) * GG;                             \
            _Pragma("unroll") for (int g = 0; g < 4; ++g)                          \
                xh[k][g] = __ldg(xp + bo + g * HH);                                \
        }                                                                          \
    }

    __half xh[2][4];
    XG_PREFETCH(0);

    for (int t = 0; t < SS; ++t) {
        const int par = t & 1;
        const __half* hsrc = g_h16[par] + (size_t)(ms * 64) * HH;
        const unsigned tgt = 8u * (unsigned)t;

        // wait for producers of chunks 0..2 of h(t-1), then start the pipeline
        if (tid == 0) {
            while (ld_acq(flg + 0 * 32) < tgt) {}
            while (ld_acq(flg + 1 * 32) < tgt) {}
            while (ld_acq(flg + 2 * 32) < tgt) {}
        }
        __syncthreads();

        float acc[2][2][4];
#pragma unroll
        for (int mi = 0; mi < 2; ++mi)
#pragma unroll
            for (int nh = 0; nh < 2; ++nh)
#pragma unroll
                for (int u = 0; u < 4; ++u) acc[mi][nh][u] = 0.f;

        H_LOAD(0, 0);
        H_LOAD(1, 1);
        H_LOAD(2, 2);
#pragma unroll 1
        for (int kc = 0; kc < 8; ++kc) {
            if (kc < 6)       cp_wait<2>();
            else if (kc == 6) cp_wait<1>();
            else              cp_wait<0>();
            if (kc < 5 && tid == 0)
                while (ld_acq(flg + (kc + 3) * 32) < tgt) {}
            __syncthreads();                 // chunk kc visible + flag kc+3 confirmed
            if (kc < 5) H_LOAD((kc + 3) & 3, kc + 3);
            const int buf = kc & 3;
#pragma unroll
            for (int kk2 = 0; kk2 < 4; ++kk2) {
                const int kk = kh * 4 + kk2;
                uint32_t a[2][4];
#pragma unroll
                for (int mi = 0; mi < 2; ++mi)
                    ldsm_x4(a[mi], &Hs[buf * HBUF +
                                       (wm * 32 + mi * 16 + (lane & 15)) * HCH_STRIDE +
                                       kk * 16 + (lane >> 4) * 8]);
                uint32_t b4[4];
                ldsm_x4(b4, &Whs[(wn * 16 + (lane & 15)) * WHS_STRIDE +
                                 kc * 128 + kk * 16 + (lane >> 4) * 8]);
#pragma unroll
                for (int mi = 0; mi < 2; ++mi) {
                    mma16816(acc[mi][0], a[mi], b4[0], b4[2]);
                    mma16816(acc[mi][1], a[mi], b4[1], b4[3]);
                }
            }
        }

        // write K-half partial gate tiles (transposed) to Gs0/Gs1
        {
            float* G = kh ? Gs1 : Gs0;
            int r = lane >> 2, c2 = (lane & 3) * 2;
#pragma unroll
            for (int mi = 0; mi < 2; ++mi)
#pragma unroll
                for (int nh = 0; nh < 2; ++nh) {
                    int col = wn * 16 + nh * 8 + c2;
                    int row = wm * 32 + mi * 16 + r;
                    G[row * GS_STRIDE + col]           = acc[mi][nh][0];
                    G[row * GS_STRIDE + col + 1]       = acc[mi][nh][1];
                    G[(row + 8) * GS_STRIDE + col]     = acc[mi][nh][2];
                    G[(row + 8) * GS_STRIDE + col + 1] = acc[mi][nh][3];
                }
        }
        __syncthreads();

        // elementwise: 2 cells/thread; c in registers; h fp16 to the other buffer
        __half* hdst = g_h16[par ^ 1] + (size_t)(ms * 64) * HH + ns * 16 + hc;
#pragma unroll
        for (int k = 0; k < 2; ++k) {
            int b = brow0 + k * 32;
            int base = b * GS_STRIDE + hc;
            float fv = Gs0[base]      + Gs1[base]      + __half2float(xh[k][0]);
            float iv = Gs0[base + 16] + Gs1[base + 16] + __half2float(xh[k][1]);
            float gv = Gs0[base + 32] + Gs1[base + 32] + __half2float(xh[k][2]);
            float ov = Gs0[base + 48] + Gs1[base + 48] + __half2float(xh[k][3]);
            cst[k] = sigm(fv) * cst[k] + sigm(iv) * tanh_a(gv);
            float hv = sigm(ov) * tanh_a(cst[k]);
            hdst[(size_t)b * HH] = __float2half(hv);
            if (t == SS - 1) g_h32[(size_t)(ms * 64 + b) * HH + ns * 16 + hc] = hv;
        }

        // publish h(t): fence all threads' stores, then bump this CTA's group counter
        __threadfence();
        __syncthreads();
        if (tid == 0) atomicAdd(myflag, 1u);
        if (t + 1 < SS) XG_PREFETCH(t + 1);   // overlaps next step's flag waits
    }
}

// ---------------- head ----------------
__global__ void lstm_head(const float* __restrict__ fc_w, const float* __restrict__ fc_b,
                          float* __restrict__ out) {
    __shared__ float hrow[HH];
    int b = blockIdx.x;
    for (int i = threadIdx.x; i < HH; i += 128) hrow[i] = g_h32[(size_t)b * HH + i];
    __syncthreads();
    int o = threadIdx.x;
    const float4* wp = (const float4*)(fc_w + (size_t)o * HH);
    float s = 0.f;
#pragma unroll 4
    for (int i = 0; i < HH / 4; ++i) {
        float4 w = wp[i];
        s += w.x * hrow[i * 4] + w.y * hrow[i * 4 + 1] + w.z * hrow[i * 4 + 2] + w.w * hrow[i * 4 + 3];
    }
    out[b * 128 + o] = s + fc_b[o];
}

extern "C" void kernel_launch(void* const* d_in, const int* in_sizes, int n_in,
                              void* d_out, int out_size) {
    const float* x    = (const float*)d_in[0];
    const float* Wx   = (const float*)d_in[1];
    const float* bW   = (const float*)d_in[2];
    const float* Wh   = (const float*)d_in[3];
    const float* bU   = (const float*)d_in[4];
    const float* fc_w = (const float*)d_in[5];
    const float* fc_b = (const float*)d_in[6];
    float* out = (float*)d_out;

    cudaFuncSetAttribute(lstm_xproj, cudaFuncAttributeMaxDynamicSharedMemorySize, P1_SMEM);
    cudaFuncSetAttribute(lstm_rec,   cudaFuncAttributeMaxDynamicSharedMemorySize, P2_SMEM);

    lstm_prep_w<<<2048, 256>>>(Wx, Wh, bW, bU);
    lstm_prep_x<<<4096, 256>>>(x);
    lstm_xproj<<<dim3(32, 1024), 256, P1_SMEM>>>();
    lstm_rec<<<NCTA2, 512, P2_SMEM>>>();
    lstm_head<<<128, 128>>>(fc_w, fc_b, out);
}

// round 14
// speedup vs baseline: 1.2902x; 1.2902x over previous
#include <cuda_runtime.h>
#include <cuda_fp16.h>
#include <cstdint>
#include <cstddef>

#define BB 128
#define SS 1024
#define II 512
#define HH 1024
#define GG 4096
#define NCTA2 128

__device__ __half g_x_h[(size_t)BB * SS * II];
__device__ __half g_Wx_h[(size_t)GG * II];
__device__ __half g_Wh_h[(size_t)GG * HH];
__device__ float  g_bsum[GG];
__device__ __half g_xg[(size_t)SS * BB * GG];   // [S][B][4H]
__device__ __half g_h16[2][BB * HH];
__device__ float  g_h32[BB * HH];
__device__ unsigned g_bar_count;
__device__ unsigned g_bar_gen;

__device__ __forceinline__ uint32_t smem_u32(const void* p) {
    return (uint32_t)__cvta_generic_to_shared(p);
}
__device__ __forceinline__ void cp_async16(void* dst, const void* src) {
    // .cg: bypass L1 (h is written by other SMs; L1 is per-SM incoherent)
    asm volatile("cp.async.cg.shared.global [%0], [%1], 16;\n" ::"r"(smem_u32(dst)), "l"(src));
}
__device__ __forceinline__ void cp_commit() { asm volatile("cp.async.commit_group;\n"); }
template <int N>
__device__ __forceinline__ void cp_wait() { asm volatile("cp.async.wait_group %0;\n" ::"n"(N)); }

__device__ __forceinline__ void ldsm_x4(uint32_t (&r)[4], const void* p) {
    asm volatile("ldmatrix.sync.aligned.m8n8.x4.shared.b16 {%0,%1,%2,%3}, [%4];\n"
                 : "=r"(r[0]), "=r"(r[1]), "=r"(r[2]), "=r"(r[3]) : "r"(smem_u32(p)));
}
__device__ __forceinline__ void mma16816(float (&d)[4], const uint32_t (&a)[4],
                                         uint32_t b0, uint32_t b1) {
    asm volatile("mma.sync.aligned.m16n8k16.row.col.f32.f16.f16.f32 "
                 "{%0,%1,%2,%3}, {%4,%5,%6,%7}, {%8,%9}, {%0,%1,%2,%3};\n"
                 : "+f"(d[0]), "+f"(d[1]), "+f"(d[2]), "+f"(d[3])
                 : "r"(a[0]), "r"(a[1]), "r"(a[2]), "r"(a[3]), "r"(b0), "r"(b1));
}
__device__ __forceinline__ float tanh_a(float x) {
    float y; asm("tanh.approx.f32 %0, %1;" : "=f"(y) : "f"(x)); return y;
}
__device__ __forceinline__ float sigm(float x) { return fmaf(tanh_a(0.5f * x), 0.5f, 0.5f); }
__device__ __forceinline__ unsigned ld_acq(const unsigned* p) {
    unsigned v;
    asm volatile("ld.acquire.gpu.b32 %0, [%1];" : "=r"(v) : "l"(p) : "memory");
    return v;
}
__device__ __forceinline__ unsigned atom_add_rel(unsigned* p, unsigned v) {
    unsigned o;
    asm volatile("atom.add.release.gpu.u32 %0, [%1], %2;" : "=r"(o) : "l"(p), "r"(v) : "memory");
    return o;
}

// ---------------- init ----------------
__global__ void lstm_prep_w(const float* __restrict__ Wx, const float* __restrict__ Wh,
                            const float* __restrict__ bW, const float* __restrict__ bU) {
    int stride = gridDim.x * blockDim.x;
    int i0 = blockIdx.x * blockDim.x + threadIdx.x;
    for (int i = i0; i < GG * HH; i += stride) g_Wh_h[i] = __float2half(Wh[i]);
    for (int i = i0; i < GG * II; i += stride) g_Wx_h[i] = __float2half(Wx[i]);
    if (i0 < GG) g_bsum[i0] = bW[i0] + bU[i0];
    if (i0 < BB * HH) { g_h16[0][i0] = __float2half(0.f); g_h16[1][i0] = __float2half(0.f); }
    if (i0 == 0) { g_bar_count = 0u; g_bar_gen = 0u; }
}
__global__ void lstm_prep_x(const float* __restrict__ x) {
    int stride = gridDim.x * blockDim.x;
    for (int i = blockIdx.x * blockDim.x + threadIdx.x; i < BB * SS * II; i += stride)
        g_x_h[i] = __float2half(x[i]);
}

// ---------------- phase 1: xg = x @ Wx^T + bsum (unchanged, known-good) ----------------
#define P1_SMEM (2 * 2 * 128 * 72 * 2)
__global__ void __launch_bounds__(256) lstm_xproj() {
    extern __shared__ __half sm1[];
    __half* As = sm1;
    __half* Bs = sm1 + 2 * 128 * 72;
    const int tid = threadIdx.x, lane = tid & 31, wid = tid >> 5;
    const int wm = wid >> 1, wn = wid & 1;
    const int n0 = blockIdx.x * 128, sblk = blockIdx.y;
    float acc[2][8][4];
#pragma unroll
    for (int mi = 0; mi < 2; ++mi)
#pragma unroll
        for (int f = 0; f < 8; ++f)
#pragma unroll
            for (int u = 0; u < 4; ++u) acc[mi][f][u] = 0.f;
#define P1_LOAD(buf, kc)                                                           \
    {                                                                              \
        int k0_ = (kc) * 64;                                                       \
        _Pragma("unroll") for (int it = 0; it < 4; ++it) {                         \
            int task = tid + it * 256, row = task >> 3, seg = task & 7;            \
            cp_async16(&As[(buf) * 9216 + row * 72 + seg * 8],                     \
                       g_x_h + ((size_t)row * SS + sblk) * II + k0_ + seg * 8);    \
            cp_async16(&Bs[(buf) * 9216 + row * 72 + seg * 8],                     \
                       g_Wx_h + (size_t)(n0 + row) * II + k0_ + seg * 8);          \
        }                                                                          \
    }
    P1_LOAD(0, 0);
    cp_commit();
#pragma unroll 1
    for (int kc = 0; kc < 8; ++kc) {
        int buf = kc & 1;
        if (kc < 7) { P1_LOAD(buf ^ 1, kc + 1); cp_commit(); cp_wait<1>(); }
        else        { cp_wait<0>(); }
        __syncthreads();
#pragma unroll
        for (int kk = 0; kk < 4; ++kk) {
            uint32_t a[2][4];
#pragma unroll
            for (int mi = 0; mi < 2; ++mi)
                ldsm_x4(a[mi], &As[buf * 9216 + (wm * 32 + mi * 16 + (lane & 15)) * 72 +
                                   kk * 16 + (lane >> 4) * 8]);
#pragma unroll
            for (int nj = 0; nj < 4; ++nj) {
                uint32_t b4[4];
                ldsm_x4(b4, &Bs[buf * 9216 + (wn * 64 + nj * 16 + (lane & 15)) * 72 +
                                kk * 16 + (lane >> 4) * 8]);
#pragma unroll
                for (int mi = 0; mi < 2; ++mi) {
                    mma16816(acc[mi][nj * 2 + 0], a[mi], b4[0], b4[2]);
                    mma16816(acc[mi][nj * 2 + 1], a[mi], b4[1], b4[3]);
                }
            }
        }
        __syncthreads();
    }
    const int r = lane >> 2, c2 = (lane & 3) * 2;
    const size_t mbase = (size_t)sblk * 128;
#pragma unroll
    for (int mi = 0; mi < 2; ++mi) {
        int mrow = wm * 32 + mi * 16 + r;
#pragma unroll
        for (int f = 0; f < 8; ++f) {
            int col = n0 + wn * 64 + f * 8 + c2;
            float b0 = g_bsum[col], b1 = g_bsum[col + 1];
            *(__half2*)(g_xg + (mbase + mrow) * (size_t)GG + col) =
                __floats2half2_rn(acc[mi][f][0] + b0, acc[mi][f][1] + b1);
            *(__half2*)(g_xg + (mbase + mrow + 8) * (size_t)GG + col) =
                __floats2half2_rn(acc[mi][f][2] + b0, acc[mi][f][3] + b1);
        }
    }
}

// ---------------- phase 2: persistent recurrence, LDSM-minimized tiling ----------------
// 128 CTAs: ms = blk>>6 (64 B-rows), ns = blk&63 (16 h-cols -> 64 gate cols).
// 8 warps (256 thr): wm = wid>>2 (32 B-rows), kh = wid&3; warp tile 32x64 over K-slice:
// within chunk kc (8 k16-steps) warp kh does steps 2kh,2kh+1. A read once, B read twice
// -> LDSM 384KB/step (was 768KB). kh partial tiles -> 4 fp32 smem buffers aliasing the
// 4 h-chunk buffers (dead after the MMA loop).
#define WHS_STRIDE 1032
#define HCH_STRIDE 136
#define GS_STRIDE  68
#define HBUF (64 * HCH_STRIDE)   /* halves; 17408 B */
#define P2_SMEM (132096 + 4 * 17408) /* 201728 B -> 1 CTA/SM */

__global__ void __launch_bounds__(256, 1) lstm_rec() {
    extern __shared__ unsigned char smraw[];
    __half* Whs = (__half*)smraw;
    __half* Hs  = (__half*)(smraw + 132096);
    const int tid = threadIdx.x, lane = tid & 31, wid = tid >> 5;
    const int wm = wid >> 2, kh = wid & 3;
    const int ms = blockIdx.x >> 6, ns = blockIdx.x & 63;
    float* Gp = (float*)(smraw + 132096 + kh * 17408);   // this warp's partial buffer

    // resident Wh slice: row j -> gate (j>>4), h-col ns*16+(j&15)
#pragma unroll 4
    for (int it = 0; it < 32; ++it) {
        int task = tid + it * 256;
        int j = task >> 7, seg = task & 127;
        int grow = (j >> 4) * HH + ns * 16 + (j & 15);
        cp_async16(&Whs[j * WHS_STRIDE + seg * 8], g_Wh_h + (size_t)grow * HH + seg * 8);
    }
    cp_commit();
    cp_wait<0>();
    __syncthreads();

    const int hc = tid & 15, brow0 = tid >> 4;   // cells (brow0 + k*16, hc), k=0..3
    float cst[4] = {0.f, 0.f, 0.f, 0.f};

#define H_LOAD(buf, kc)                                                            \
    {                                                                              \
        _Pragma("unroll") for (int it = 0; it < 4; ++it) {                         \
            int task = tid + it * 256, row = task >> 4, seg = task & 15;           \
            cp_async16(&Hs[(buf) * HBUF + row * HCH_STRIDE + seg * 8],             \
                       hsrc + (size_t)row * HH + (kc) * 128 + seg * 8);            \
        }                                                                          \
        cp_commit();                                                               \
    }
#define XG_PREFETCH(tt)                                                            \
    {                                                                              \
        const __half* xp = g_xg + ((size_t)(tt) * BB + ms * 64) * GG + ns * 16 + hc; \
        _Pragma("unroll") for (int k = 0; k < 4; ++k) {                            \
            size_t bo = (size_t)(brow0 + k * 16) * GG;                             \
            _Pragma("unroll") for (int g = 0; g < 4; ++g)                          \
                xh[k][g] = __ldg(xp + bo + g * HH);                                \
        }                                                                          \
    }

    __half xh[4][4];
    XG_PREFETCH(0);

    for (int t = 0; t < SS; ++t) {
        const int par = t & 1;
        const __half* hsrc = g_h16[par] + (size_t)(ms * 64) * HH;

        // wait: all CTAs finished step t-1 (gen == t); xg for step t already in regs
        if (t > 0) {
            if (tid == 0)
                while (ld_acq(&g_bar_gen) < (unsigned)t) {}
            __syncthreads();
        }

        float acc[2][8][4];
#pragma unroll
        for (int mi = 0; mi < 2; ++mi)
#pragma unroll
            for (int nj = 0; nj < 8; ++nj)
#pragma unroll
                for (int u = 0; u < 4; ++u) acc[mi][nj][u] = 0.f;

        H_LOAD(0, 0);
        H_LOAD(1, 1);
        H_LOAD(2, 2);
#pragma unroll 1
        for (int kc = 0; kc < 8; ++kc) {
            if (kc < 6)       cp_wait<2>();
            else if (kc == 6) cp_wait<1>();
            else              cp_wait<0>();
            __syncthreads();
            if (kc < 5) H_LOAD((kc + 3) & 3, kc + 3);
            const int buf = kc & 3;
#pragma unroll
            for (int j = 0; j < 2; ++j) {
                const int kk = kh * 2 + j;
                uint32_t a[2][4];
#pragma unroll
                for (int mi = 0; mi < 2; ++mi)
                    ldsm_x4(a[mi], &Hs[buf * HBUF +
                                       (wm * 32 + mi * 16 + (lane & 15)) * HCH_STRIDE +
                                       kk * 16 + (lane >> 4) * 8]);
#pragma unroll
                for (int nb = 0; nb < 4; ++nb) {
                    uint32_t b4[4];
                    ldsm_x4(b4, &Whs[(nb * 16 + (lane & 15)) * WHS_STRIDE +
                                     kc * 128 + kk * 16 + (lane >> 4) * 8]);
#pragma unroll
                    for (int mi = 0; mi < 2; ++mi) {
                        mma16816(acc[mi][nb * 2 + 0], a[mi], b4[0], b4[2]);
                        mma16816(acc[mi][nb * 2 + 1], a[mi], b4[1], b4[3]);
                    }
                }
            }
        }
        __syncthreads();   // all warps done reading h buffers -> partials may alias them

        // write partial gate tiles (one fp32 buffer per kh)
        {
            int r = lane >> 2, c2 = (lane & 3) * 2;
#pragma unroll
            for (int mi = 0; mi < 2; ++mi) {
                int row = wm * 32 + mi * 16 + r;
#pragma unroll
                for (int nj = 0; nj < 8; ++nj) {
                    int col = nj * 8 + c2;
                    Gp[row * GS_STRIDE + col]           = acc[mi][nj][0];
                    Gp[row * GS_STRIDE + col + 1]       = acc[mi][nj][1];
                    Gp[(row + 8) * GS_STRIDE + col]     = acc[mi][nj][2];
                    Gp[(row + 8) * GS_STRIDE + col + 1] = acc[mi][nj][3];
                }
            }
        }
        __syncthreads();

        // combine 4 partials, activations, h fp16 to the other buffer
        const float* G0 = (const float*)(smraw + 132096);
        __half* hdst = g_h16[par ^ 1] + (size_t)(ms * 64) * HH + ns * 16 + hc;
#pragma unroll
        for (int k = 0; k < 4; ++k) {
            int b = brow0 + k * 16;
            float gv4[4];
#pragma unroll
            for (int gi = 0; gi < 4; ++gi) {
                int off = b * GS_STRIDE + gi * 16 + hc;
                float s = G0[off] + G0[off + 4352] + G0[off + 8704] + G0[off + 13056];
                gv4[gi] = s + __half2float(xh[k][gi]);
            }
            cst[k] = sigm(gv4[0]) * cst[k] + sigm(gv4[1]) * tanh_a(gv4[2]);
            float hv = sigm(gv4[3]) * tanh_a(cst[k]);
            hdst[(size_t)b * HH] = __float2half(hv);
            if (t == SS - 1) g_h32[(size_t)(ms * 64 + b) * HH + ns * 16 + hc] = hv;
        }

        // publish h(t): bar.sync gives happens-before into tid0; release-add publishes
        __syncthreads();
        if (tid == 0) {
            unsigned old = atom_add_rel(&g_bar_count, 1u);
            if (old == (unsigned)(NCTA2 - 1)) {
                *(volatile unsigned*)&g_bar_count = 0u;
                atom_add_rel(&g_bar_gen, 1u);
            }
        }
        if (t + 1 < SS) XG_PREFETCH(t + 1);   // overlaps the barrier wait
    }
}

// ---------------- head ----------------
__global__ void lstm_head(const float* __restrict__ fc_w, const float* __restrict__ fc_b,
                          float* __restrict__ out) {
    __shared__ float hrow[HH];
    int b = blockIdx.x;
    for (int i = threadIdx.x; i < HH; i += 128) hrow[i] = g_h32[(size_t)b * HH + i];
    __syncthreads();
    int o = threadIdx.x;
    const float4* wp = (const float4*)(fc_w + (size_t)o * HH);
    float s = 0.f;
#pragma unroll 4
    for (int i = 0; i < HH / 4; ++i) {
        float4 w = wp[i];
        s += w.x * hrow[i * 4] + w.y * hrow[i * 4 + 1] + w.z * hrow[i * 4 + 2] + w.w * hrow[i * 4 + 3];
    }
    out[b * 128 + o] = s + fc_b[o];
}

extern "C" void kernel_launch(void* const* d_in, const int* in_sizes, int n_in,
                              void* d_out, int out_size) {
    const float* x    = (const float*)d_in[0];
    const float* Wx   = (const float*)d_in[1];
    const float* bW   = (const float*)d_in[2];
    const float* Wh   = (const float*)d_in[3];
    const float* bU   = (const float*)d_in[4];
    const float* fc_w = (const float*)d_in[5];
    const float* fc_b = (const float*)d_in[6];
    float* out = (float*)d_out;

    cudaFuncSetAttribute(lstm_xproj, cudaFuncAttributeMaxDynamicSharedMemorySize, P1_SMEM);
    cudaFuncSetAttribute(lstm_rec,   cudaFuncAttributeMaxDynamicSharedMemorySize, P2_SMEM);

    lstm_prep_w<<<2048, 256>>>(Wx, Wh, bW, bU);
    lstm_prep_x<<<4096, 256>>>(x);
    lstm_xproj<<<dim3(32, 1024), 256, P1_SMEM>>>();
    lstm_rec<<<NCTA2, 256, P2_SMEM>>>();
    lstm_head<<<128, 128>>>(fc_w, fc_b, out);
}

// round 16
// speedup vs baseline: 1.3963x; 1.0822x over previous
#include <cuda_runtime.h>
#include <cuda_fp16.h>
#include <cstdint>
#include <cstddef>

#define BB 128
#define SS 1024
#define II 512
#define HH 1024
#define GG 4096
#define NCTA2 128

__device__ __half g_x_h[(size_t)BB * SS * II];
__device__ __half g_Wx_h[(size_t)GG * II];
__device__ __half g_Wh_h[(size_t)GG * HH];
__device__ float  g_bsum[GG];
__device__ __half g_xg[(size_t)SS * BB * GG];   // [S][B][4H]
__device__ __half g_h16[2][BB * HH];
__device__ float  g_h32[BB * HH];
__device__ unsigned g_cnt[64];   // per-ms barrier count at [ms*32]
__device__ unsigned g_gen[64];   // per-ms generation at [ms*32]

__device__ __forceinline__ uint32_t smem_u32(const void* p) {
    return (uint32_t)__cvta_generic_to_shared(p);
}
__device__ __forceinline__ void cp_async16(void* dst, const void* src) {
    asm volatile("cp.async.cg.shared.global [%0], [%1], 16;\n" ::"r"(smem_u32(dst)), "l"(src));
}
__device__ __forceinline__ void cp_async16_s(uint32_t dst, const void* src) {
    asm volatile("cp.async.cg.shared.global [%0], [%1], 16;\n" ::"r"(dst), "l"(src));
}
__device__ __forceinline__ void cp_commit() { asm volatile("cp.async.commit_group;\n"); }
template <int N>
__device__ __forceinline__ void cp_wait() { asm volatile("cp.async.wait_group %0;\n" ::"n"(N)); }

__device__ __forceinline__ void ldsm_x4(uint32_t (&r)[4], const void* p) {
    asm volatile("ldmatrix.sync.aligned.m8n8.x4.shared.b16 {%0,%1,%2,%3}, [%4];\n"
                 : "=r"(r[0]), "=r"(r[1]), "=r"(r[2]), "=r"(r[3]) : "r"(smem_u32(p)));
}
__device__ __forceinline__ void mma16816(float (&d)[4], const uint32_t (&a)[4],
                                         uint32_t b0, uint32_t b1) {
    asm volatile("mma.sync.aligned.m16n8k16.row.col.f32.f16.f16.f32 "
                 "{%0,%1,%2,%3}, {%4,%5,%6,%7}, {%8,%9}, {%0,%1,%2,%3};\n"
                 : "+f"(d[0]), "+f"(d[1]), "+f"(d[2]), "+f"(d[3])
                 : "r"(a[0]), "r"(a[1]), "r"(a[2]), "r"(a[3]), "r"(b0), "r"(b1));
}
__device__ __forceinline__ float tanh_a(float x) {
    float y; asm("tanh.approx.f32 %0, %1;" : "=f"(y) : "f"(x)); return y;
}
__device__ __forceinline__ float sigm(float x) { return fmaf(tanh_a(0.5f * x), 0.5f, 0.5f); }
__device__ __forceinline__ unsigned ld_acq(const unsigned* p) {
    unsigned v;
    asm volatile("ld.acquire.gpu.b32 %0, [%1];" : "=r"(v) : "l"(p) : "memory");
    return v;
}
__device__ __forceinline__ unsigned atom_add_rel(unsigned* p, unsigned v) {
    unsigned o;
    asm volatile("atom.add.release.gpu.u32 %0, [%1], %2;" : "=r"(o) : "l"(p), "r"(v) : "memory");
    return o;
}
__device__ __forceinline__ void mbar_init(uint32_t a, uint32_t n) {
    asm volatile("mbarrier.init.shared.b64 [%0], %1;" ::"r"(a), "r"(n) : "memory");
}
__device__ __forceinline__ void mbar_arrive(uint32_t a) {
    asm volatile("mbarrier.arrive.shared.b64 _, [%0];" ::"r"(a) : "memory");
}
__device__ __forceinline__ void cp_async_mbar_arrive_noinc(uint32_t a) {
    // .noinc: completion-arrive counts against the init expected count (32 lanes).
    asm volatile("cp.async.mbarrier.arrive.noinc.shared.b64 [%0];" ::"r"(a) : "memory");
}
__device__ __forceinline__ void mbar_wait(uint32_t a, uint32_t parity) {
    uint32_t done = 0;
    while (!done)
        asm volatile("{\n\t.reg .pred p;\n\t"
                     "mbarrier.try_wait.parity.shared.b64 p, [%1], %2;\n\t"
                     "selp.b32 %0, 1, 0, p;\n\t}"
                     : "=r"(done) : "r"(a), "r"(parity) : "memory");
}
__device__ __forceinline__ void bar256() {
    asm volatile("bar.sync 1, 256;" ::: "memory");
}

// ---------------- init ----------------
__global__ void lstm_prep_w(const float* __restrict__ Wx, const float* __restrict__ Wh,
                            const float* __restrict__ bW, const float* __restrict__ bU) {
    int stride = gridDim.x * blockDim.x;
    int i0 = blockIdx.x * blockDim.x + threadIdx.x;
    for (int i = i0; i < GG * HH; i += stride) g_Wh_h[i] = __float2half(Wh[i]);
    for (int i = i0; i < GG * II; i += stride) g_Wx_h[i] = __float2half(Wx[i]);
    if (i0 < GG) g_bsum[i0] = bW[i0] + bU[i0];
    if (i0 < BB * HH) { g_h16[0][i0] = __float2half(0.f); g_h16[1][i0] = __float2half(0.f); }
    if (i0 < 64) { g_cnt[i0] = 0u; g_gen[i0] = 0u; }
}
__global__ void lstm_prep_x(const float* __restrict__ x) {
    int stride = gridDim.x * blockDim.x;
    for (int i = blockIdx.x * blockDim.x + threadIdx.x; i < BB * SS * II; i += stride)
        g_x_h[i] = __float2half(x[i]);
}

// ---------------- phase 1: xg = x @ Wx^T + bsum (unchanged, known-good) ----------------
#define P1_SMEM (2 * 2 * 128 * 72 * 2)
__global__ void __launch_bounds__(256) lstm_xproj() {
    extern __shared__ __half sm1[];
    __half* As = sm1;
    __half* Bs = sm1 + 2 * 128 * 72;
    const int tid = threadIdx.x, lane = tid & 31, wid = tid >> 5;
    const int wm = wid >> 1, wn = wid & 1;
    const int n0 = blockIdx.x * 128, sblk = blockIdx.y;
    float acc[2][8][4];
#pragma unroll
    for (int mi = 0; mi < 2; ++mi)
#pragma unroll
        for (int f = 0; f < 8; ++f)
#pragma unroll
            for (int u = 0; u < 4; ++u) acc[mi][f][u] = 0.f;
#define P1_LOAD(buf, kc)                                                           \
    {                                                                              \
        int k0_ = (kc) * 64;                                                       \
        _Pragma("unroll") for (int it = 0; it < 4; ++it) {                         \
            int task = tid + it * 256, row = task >> 3, seg = task & 7;            \
            cp_async16(&As[(buf) * 9216 + row * 72 + seg * 8],                     \
                       g_x_h + ((size_t)row * SS + sblk) * II + k0_ + seg * 8);    \
            cp_async16(&Bs[(buf) * 9216 + row * 72 + seg * 8],                     \
                       g_Wx_h + (size_t)(n0 + row) * II + k0_ + seg * 8);          \
        }                                                                          \
    }
    P1_LOAD(0, 0);
    cp_commit();
#pragma unroll 1
    for (int kc = 0; kc < 8; ++kc) {
        int buf = kc & 1;
        if (kc < 7) { P1_LOAD(buf ^ 1, kc + 1); cp_commit(); cp_wait<1>(); }
        else        { cp_wait<0>(); }
        __syncthreads();
#pragma unroll
        for (int kk = 0; kk < 4; ++kk) {
            uint32_t a[2][4];
#pragma unroll
            for (int mi = 0; mi < 2; ++mi)
                ldsm_x4(a[mi], &As[buf * 9216 + (wm * 32 + mi * 16 + (lane & 15)) * 72 +
                                   kk * 16 + (lane >> 4) * 8]);
#pragma unroll
            for (int nj = 0; nj < 4; ++nj) {
                uint32_t b4[4];
                ldsm_x4(b4, &Bs[buf * 9216 + (wn * 64 + nj * 16 + (lane & 15)) * 72 +
                                kk * 16 + (lane >> 4) * 8]);
#pragma unroll
                for (int mi = 0; mi < 2; ++mi) {
                    mma16816(acc[mi][nj * 2 + 0], a[mi], b4[0], b4[2]);
                    mma16816(acc[mi][nj * 2 + 1], a[mi], b4[1], b4[3]);
                }
            }
        }
        __syncthreads();
    }
    const int r = lane >> 2, c2 = (lane & 3) * 2;
    const size_t mbase = (size_t)sblk * 128;
#pragma unroll
    for (int mi = 0; mi < 2; ++mi) {
        int mrow = wm * 32 + mi * 16 + r;
#pragma unroll
        for (int f = 0; f < 8; ++f) {
            int col = n0 + wn * 64 + f * 8 + c2;
            float b0 = g_bsum[col], b1 = g_bsum[col + 1];
            *(__half2*)(g_xg + (mbase + mrow) * (size_t)GG + col) =
                __floats2half2_rn(acc[mi][f][0] + b0, acc[mi][f][1] + b1);
            *(__half2*)(g_xg + (mbase + mrow + 8) * (size_t)GG + col) =
                __floats2half2_rn(acc[mi][f][2] + b0, acc[mi][f][3] + b1);
        }
    }
}

// ---------------- phase 2: warp-specialized persistent recurrence ----------------
// 128 CTAs: ms = blk>>6 (64 B-rows), ns = blk&63 (16 h-cols -> 64 gate cols).
// 9 warps (288 thr): warps 0-7 compute (wm=wid>>2, kh=wid&3); warp 8 = producer
// (polls group gen, streams all 8 h-chunks via cp.async + mbarrier .noinc arrives).
// 4 buffers, chunk kc -> buffer kc&3; buffer use index u = 2t + (kc>>2); parities static.
#define WHS_STRIDE 1032
#define HCH_STRIDE 136
#define GS_STRIDE  68
#define HBUF (64 * HCH_STRIDE)         /* halves */
#define WH_OFF 1024
#define HS_OFF (1024 + 132096)          /* 133120 */
#define P2_SMEM (HS_OFF + 4 * 17408)    /* 202752 -> 1 CTA/SM */

__global__ void __launch_bounds__(288, 1) lstm_rec() {
    extern __shared__ unsigned char smraw[];
    const uint32_t sbase = smem_u32(smraw);
    __half* Whs = (__half*)(smraw + WH_OFF);
    __half* Hs  = (__half*)(smraw + HS_OFF);
    const int tid = threadIdx.x, lane = tid & 31, wid = tid >> 5;
    const int ms = blockIdx.x >> 6, ns = blockIdx.x & 63;
    const uint32_t fullb = sbase;        // full[b] at sbase + b*8
    const uint32_t emptyb = sbase + 32;  // empty[b] at sbase + 32 + b*8

    if (tid == 0) {
#pragma unroll
        for (int b = 0; b < 4; ++b) {
            mbar_init(fullb + b * 8, 32);   // 32 producer-lane .noinc completion arrives
            mbar_init(emptyb + b * 8, 8);   // 8 compute warps arrive per consume
        }
    }
    // resident Wh slice (compute threads): row j -> gate (j>>4), h-col ns*16+(j&15)
    if (tid < 256) {
#pragma unroll 4
        for (int it = 0; it < 32; ++it) {
            int task = tid + it * 256;
            int j = task >> 7, seg = task & 127;
            int grow = (j >> 4) * HH + ns * 16 + (j & 15);
            cp_async16(&Whs[j * WHS_STRIDE + seg * 8], g_Wh_h + (size_t)grow * HH + seg * 8);
        }
        cp_commit();
        cp_wait<0>();
    }
    __syncthreads();   // mbarriers + Wh visible to all 288

    if (wid == 8) {
        // ---------------- producer warp ----------------
        unsigned* const genp = &g_gen[ms * 32];
        for (int t = 0; t < SS; ++t) {
            if (t > 0) {
                if (lane == 0)
                    while (ld_acq(genp) < (unsigned)t) {}
                __syncwarp();
            }
            const __half* hsrc = g_h16[t & 1] + (size_t)(ms * 64) * HH;
#pragma unroll 1
            for (int kc = 0; kc < 8; ++kc) {
                const int b = kc & 3, hi = kc >> 2;
                if (t > 0 || hi)                       // u = 2t+hi > 0
                    mbar_wait(emptyb + b * 8, hi ^ 1); // wait completion of phase u-1
                const uint32_t dbase = smem_u32(Hs) + (uint32_t)b * (HBUF * 2);
#pragma unroll
                for (int i = 0; i < 32; ++i) {
                    int o = lane + 32 * i;
                    int row = o >> 4, seg = o & 15;
                    cp_async16_s(dbase + row * (HCH_STRIDE * 2) + seg * 16,
                                 hsrc + (size_t)row * HH + kc * 128 + seg * 8);
                }
                cp_async_mbar_arrive_noinc(fullb + b * 8);
            }
        }
        return;
    }

    // ---------------- compute warps (wid 0-7) ----------------
    const int wm = wid >> 2, kh = wid & 3;
    float* Gp = (float*)(smraw + HS_OFF + kh * 17408);   // partial buffer (aliases h bufs)
    const float* G0 = (const float*)(smraw + HS_OFF);
    const int hc = tid & 15, brow0 = tid >> 4;   // cells (brow0 + k*16, hc)
    float cst[4] = {0.f, 0.f, 0.f, 0.f};

#define XG_PREFETCH(tt)                                                              \
    {                                                                                \
        const __half* xp = g_xg + ((size_t)(tt) * BB + ms * 64) * GG + ns * 16 + hc; \
        _Pragma("unroll") for (int k = 0; k < 4; ++k) {                              \
            size_t bo = (size_t)(brow0 + k * 16) * GG;                               \
            _Pragma("unroll") for (int g = 0; g < 4; ++g)                            \
                xh[k][g] = __ldg(xp + bo + g * HH);                                  \
        }                                                                            \
    }

    __half xh[4][4];
    XG_PREFETCH(0);

    for (int t = 0; t < SS; ++t) {
        float acc[2][8][4];
#pragma unroll
        for (int mi = 0; mi < 2; ++mi)
#pragma unroll
            for (int nj = 0; nj < 8; ++nj)
#pragma unroll
                for (int u = 0; u < 4; ++u) acc[mi][nj][u] = 0.f;

#pragma unroll 1
        for (int kc = 0; kc < 8; ++kc) {
            const int b = kc & 3, hi = kc >> 2;
            mbar_wait(fullb + b * 8, hi);   // all 32 lanes wait phase u=2t+hi
#pragma unroll
            for (int j = 0; j < 2; ++j) {
                const int kk = kh * 2 + j;
                uint32_t a[2][4];
#pragma unroll
                for (int mi = 0; mi < 2; ++mi)
                    ldsm_x4(a[mi], &Hs[b * HBUF +
                                       (wm * 32 + mi * 16 + (lane & 15)) * HCH_STRIDE +
                                       kk * 16 + (lane >> 4) * 8]);
#pragma unroll
                for (int nb = 0; nb < 4; ++nb) {
                    uint32_t b4[4];
                    ldsm_x4(b4, &Whs[(nb * 16 + (lane & 15)) * WHS_STRIDE +
                                     kc * 128 + kk * 16 + (lane >> 4) * 8]);
#pragma unroll
                    for (int mi = 0; mi < 2; ++mi) {
                        mma16816(acc[mi][nb * 2 + 0], a[mi], b4[0], b4[2]);
                        mma16816(acc[mi][nb * 2 + 1], a[mi], b4[1], b4[3]);
                    }
                }
            }
            if (lane == 0) mbar_arrive(emptyb + b * 8);
        }
        bar256();   // all compute warps done reading h buffers -> partials may alias

        {
            int r = lane >> 2, c2 = (lane & 3) * 2;
#pragma unroll
            for (int mi = 0; mi < 2; ++mi) {
                int row = wm * 32 + mi * 16 + r;
#pragma unroll
                for (int nj = 0; nj < 8; ++nj) {
                    int col = nj * 8 + c2;
                    Gp[row * GS_STRIDE + col]           = acc[mi][nj][0];
                    Gp[row * GS_STRIDE + col + 1]       = acc[mi][nj][1];
                    Gp[(row + 8) * GS_STRIDE + col]     = acc[mi][nj][2];
                    Gp[(row + 8) * GS_STRIDE + col + 1] = acc[mi][nj][3];
                }
            }
        }
        bar256();

        const int par = t & 1;
        __half* hdst = g_h16[par ^ 1] + (size_t)(ms * 64) * HH + ns * 16 + hc;
#pragma unroll
        for (int k = 0; k < 4; ++k) {
            int b = brow0 + k * 16;
            float gv4[4];
#pragma unroll
            for (int gi = 0; gi < 4; ++gi) {
                int off = b * GS_STRIDE + gi * 16 + hc;
                float s = G0[off] + G0[off + 4352] + G0[off + 8704] + G0[off + 13056];
                gv4[gi] = s + __half2float(xh[k][gi]);
            }
            cst[k] = sigm(gv4[0]) * cst[k] + sigm(gv4[1]) * tanh_a(gv4[2]);
            float hv = sigm(gv4[3]) * tanh_a(cst[k]);
            hdst[(size_t)b * HH] = __float2half(hv);
            if (t == SS - 1) g_h32[(size_t)(ms * 64 + b) * HH + ns * 16 + hc] = hv;
        }

        bar256();   // h stores of all compute threads happen-before tid0's release
        if (tid == 0) {
            unsigned old = atom_add_rel(&g_cnt[ms * 32], 1u);
            if (old == 63u) {
                *(volatile unsigned*)&g_cnt[ms * 32] = 0u;
                atom_add_rel(&g_gen[ms * 32], 1u);
            }
        }
        if (t + 1 < SS) XG_PREFETCH(t + 1);   // overlaps the producer's gen wait
    }
}

// ---------------- head ----------------
__global__ void lstm_head(const float* __restrict__ fc_w, const float* __restrict__ fc_b,
                          float* __restrict__ out) {
    __shared__ float hrow[HH];
    int b = blockIdx.x;
    for (int i = threadIdx.x; i < HH; i += 128) hrow[i] = g_h32[(size_t)b * HH + i];
    __syncthreads();
    int o = threadIdx.x;
    const float4* wp = (const float4*)(fc_w + (size_t)o * HH);
    float s = 0.f;
#pragma unroll 4
    for (int i = 0; i < HH / 4; ++i) {
        float4 w = wp[i];
        s += w.x * hrow[i * 4] + w.y * hrow[i * 4 + 1] + w.z * hrow[i * 4 + 2] + w.w * hrow[i * 4 + 3];
    }
    out[b * 128 + o] = s + fc_b[o];
}

extern "C" void kernel_launch(void* const* d_in, const int* in_sizes, int n_in,
                              void* d_out, int out_size) {
    const float* x    = (const float*)d_in[0];
    const float* Wx   = (const float*)d_in[1];
    const float* bW   = (const float*)d_in[2];
    const float* Wh   = (const float*)d_in[3];
    const float* bU   = (const float*)d_in[4];
    const float* fc_w = (const float*)d_in[5];
    const float* fc_b = (const float*)d_in[6];
    float* out = (float*)d_out;

    cudaFuncSetAttribute(lstm_xproj, cudaFuncAttributeMaxDynamicSharedMemorySize, P1_SMEM);
    cudaFuncSetAttribute(lstm_rec,   cudaFuncAttributeMaxDynamicSharedMemorySize, P2_SMEM);

    lstm_prep_w<<<2048, 256>>>(Wx, Wh, bW, bU);
    lstm_prep_x<<<4096, 256>>>(x);
    lstm_xproj<<<dim3(32, 1024), 256, P1_SMEM>>>();
    lstm_rec<<<NCTA2, 288, P2_SMEM>>>();
    lstm_head<<<128, 128>>>(fc_w, fc_b, out);
}